// round 6
// baseline (speedup 1.0000x reference)
#include <cuda_runtime.h>
#include <cuda_bf16.h>

// Problem constants
#define BV     32000   // vocab
#define EE     256     // embed dim
#define HH     512     // hidden
#define SS     128     // enc seq len
#define TT     64      // dec len
#define BB     32      // batch
#define NSTEP  63      // T_DEC - 1
#define H3     1536    // 3*H
#define OUT_PRED (64512000LL)   // B * NSTEP * V
#define NB     96      // persistent recurrence blocks (all-resident, 1 wave)

// ---------------- scratch (device globals; no allocation allowed) ----------
__device__ float g_encCat[4096 * 2048];           // [b*128+s][0:512)=enc@W1, [512:2048)=enc@Wx_top
__device__ float g_gxemb [NSTEP * BB * H3];       // emb@Wx_bot + b_g, all steps
__device__ float g_h     [NSTEP * BB * HH];       // h_t for all steps
__device__ float g_hW2   [BB * HH];
__device__ float g_ghzr  [BB * 1024];
__device__ float g_attn  [BB * SS];
__device__ float g_z     [BB * HH];
__device__ float g_rh    [BB * HH];
__device__ float g_gx3   [BB * HH];

// ---------------- helpers ---------------------------------------------------
__device__ __forceinline__ unsigned long long dup2(float b) {
    unsigned long long r;
    unsigned int u = __float_as_uint(b);
    asm("mov.b64 %0, {%1, %1};" : "=l"(r) : "r"(u));
    return r;
}
__device__ __forceinline__ void fma2(unsigned long long& d,
                                     unsigned long long a,
                                     unsigned long long b) {
    asm("fma.rn.f32x2 %0, %1, %2, %3;" : "=l"(d) : "l"(a), "l"(b), "l"(d));
}
// exact-identity tanh/sigmoid (used for gates; cheap there)
__device__ __forceinline__ float fast_tanh(float x) {
    float e = __expf(2.0f * x);
    return 1.0f - 2.0f / (e + 1.0f);
}
__device__ __forceinline__ float fast_sig(float x) {
    return 1.0f / (1.0f + __expf(-x));
}
// HW tanh approximation: 1 MUFU, abs err ~6e-4 (used only for attention scores)
__device__ __forceinline__ float tanh_approx(float x) {
    float y;
    asm("tanh.approx.f32 %0, %1;" : "=f"(y) : "f"(x));
    return y;
}

// ---------------- grid barrier (all NB blocks resident => safe) -------------
__device__ unsigned int g_cnt = 0;
__device__ volatile unsigned int g_gen = 0;
__device__ __forceinline__ void gbar() {
    __syncthreads();
    if (threadIdx.x == 0) {
        unsigned int gen = g_gen;
        __threadfence();
        unsigned int a = atomicAdd(&g_cnt, 1u);
        if (a == NB - 1) {
            atomicExch(&g_cnt, 0u);
            __threadfence();
            atomicAdd((unsigned int*)&g_gen, 1u);
        } else {
            while (g_gen == gen) { }
            __threadfence();
        }
    }
    __syncthreads();
}

// ---------------- generic 128x128 tiled fp32 GEMM with f32x2 FMAs -----------
// MODE 0: C=g_encCat : A=enc(4096x512),         B=[W1 | Wx_top](512x2048)
// MODE 1: C=g_gxemb  : A=emb[tok(m)](2016x256), B=Wx_bot(256x1536), +b_g
// MODE 2: C=preds    : A=g_h(2016x512),         B=Wo(512x32000), +bo, scatter
template<int MODE>
__global__ __launch_bounds__(256, 2)
void gemm_k(const float* __restrict__ A,  const float* __restrict__ W1,
            const float* __restrict__ Wx, const float* __restrict__ Wo,
            const float* __restrict__ bias,
            const int*   __restrict__ dinp, const int* __restrict__ dtgt,
            const float* __restrict__ emb, float* __restrict__ C,
            int M, int K)
{
    __shared__ __align__(16) float As[16][132];
    __shared__ __align__(16) float Bs[16][132];

    const int tid = threadIdx.x;
    const int tx = tid & 15;
    const int ty = tid >> 4;
    const int bn = blockIdx.x, bm = blockIdx.y;

    unsigned long long acc[4][8];
#pragma unroll
    for (int i = 0; i < 4; i++)
#pragma unroll
        for (int j = 0; j < 8; j++) acc[i][j] = 0ULL;

    const int nTiles = K >> 4;
    for (int kt = 0; kt < nTiles; ++kt) {
#pragma unroll
        for (int q = 0; q < 2; q++) {
            int l = tid * 2 + q;          // 0..511
            int r = l >> 2;
            int cseg = l & 3;
            int rowg = bm * 128 + r; if (rowg > M - 1) rowg = M - 1;
            const float* ap;
            if (MODE == 1) {
                int t = rowg >> 5, b = rowg & 31;
                int tok = (t == 0) ? dinp[b] : dtgt[b * TT + t];
                ap = emb + (long long)tok * EE;
            } else if (MODE == 2) {
                ap = g_h + (long long)rowg * HH;
            } else {
                ap = A + (long long)rowg * K;
            }
            float4 v = *reinterpret_cast<const float4*>(ap + kt * 16 + cseg * 4);
            As[cseg * 4 + 0][r] = v.x; As[cseg * 4 + 1][r] = v.y;
            As[cseg * 4 + 2][r] = v.z; As[cseg * 4 + 3][r] = v.w;
            int kr = l >> 5;
            int nseg = l & 31;
            int kg = kt * 16 + kr;
            int n = bn * 128 + nseg * 4;
            const float* bp;
            if (MODE == 0) {
                bp = (n < 512) ? (W1 + (long long)kg * 512 + n)
                               : (Wx + (long long)kg * H3 + (n - 512));
            } else if (MODE == 1) {
                bp = Wx + (long long)(512 + kg) * H3 + n;
            } else {
                bp = Wo + (long long)kg * BV + n;
            }
            *reinterpret_cast<float4*>(&Bs[kr][nseg * 4]) =
                *reinterpret_cast<const float4*>(bp);
        }
        __syncthreads();
#pragma unroll
        for (int k = 0; k < 16; k++) {
            const unsigned long long* arow =
                reinterpret_cast<const unsigned long long*>(&As[k][0]);
            unsigned long long a0 = arow[ty * 4 + 0];
            unsigned long long a1 = arow[ty * 4 + 1];
            unsigned long long a2 = arow[ty * 4 + 2];
            unsigned long long a3 = arow[ty * 4 + 3];
            float4 b0 = *reinterpret_cast<const float4*>(&Bs[k][tx * 4]);
            float4 b1 = *reinterpret_cast<const float4*>(&Bs[k][64 + tx * 4]);
            float bf[8] = {b0.x, b0.y, b0.z, b0.w, b1.x, b1.y, b1.z, b1.w};
#pragma unroll
            for (int j = 0; j < 8; j++) {
                unsigned long long dj = dup2(bf[j]);
                fma2(acc[0][j], a0, dj);
                fma2(acc[1][j], a1, dj);
                fma2(acc[2][j], a2, dj);
                fma2(acc[3][j], a3, dj);
            }
        }
        __syncthreads();
    }

    const int nA = bn * 128 + tx * 4;
    const int nB = nA + 64;
#pragma unroll
    for (int i2 = 0; i2 < 4; i2++) {
#pragma unroll
        for (int p = 0; p < 2; p++) {
            int m = bm * 128 + ty * 8 + i2 * 2 + p;
            if (m >= M) continue;
            float vals[8];
#pragma unroll
            for (int j = 0; j < 8; j++) {
                unsigned long long u = acc[i2][j];
                unsigned int w = (p == 0) ? (unsigned int)u
                                          : (unsigned int)(u >> 32);
                vals[j] = __uint_as_float(w);
            }
            if (MODE == 0) {
                float* cp = g_encCat + (long long)m * 2048;
                *reinterpret_cast<float4*>(cp + nA) =
                    make_float4(vals[0], vals[1], vals[2], vals[3]);
                *reinterpret_cast<float4*>(cp + nB) =
                    make_float4(vals[4], vals[5], vals[6], vals[7]);
            } else if (MODE == 1) {
                float* cp = g_gxemb + (long long)m * H3;
                float4 ba = *reinterpret_cast<const float4*>(bias + nA);
                float4 bb = *reinterpret_cast<const float4*>(bias + nB);
                *reinterpret_cast<float4*>(cp + nA) =
                    make_float4(vals[0] + ba.x, vals[1] + ba.y,
                                vals[2] + ba.z, vals[3] + ba.w);
                *reinterpret_cast<float4*>(cp + nB) =
                    make_float4(vals[4] + bb.x, vals[5] + bb.y,
                                vals[6] + bb.z, vals[7] + bb.w);
            } else {
                int t = m >> 5, b = m & 31;   // m = t*32 + b
                float* cp = C + (long long)b * (NSTEP * (long long)BV)
                              + (long long)t * BV;
                float4 ba = *reinterpret_cast<const float4*>(bias + nA);
                float4 bb = *reinterpret_cast<const float4*>(bias + nB);
                *reinterpret_cast<float4*>(cp + nA) =
                    make_float4(vals[0] + ba.x, vals[1] + ba.y,
                                vals[2] + ba.z, vals[3] + ba.w);
                *reinterpret_cast<float4*>(cp + nB) =
                    make_float4(vals[4] + bb.x, vals[5] + bb.y,
                                vals[6] + bb.z, vals[7] + bb.w);
            }
        }
    }
}

// ---------------- persistent fused recurrence (63 steps, one launch) --------
// 96 blocks x 256 threads, 4 phases per step separated by grid barriers.
__global__ __launch_bounds__(256)
void k_recur(const float* __restrict__ dec_hidden,
             const float* __restrict__ W2,
             const float* __restrict__ Wh,
             const float* __restrict__ v_a)
{
    const int bid = blockIdx.x;
    const int tid = threadIdx.x;
    __shared__ float s_hv[HH];
    __shared__ float s_vv[HH];
    __shared__ float s_sc[SS];
    __shared__ float s_red[SS];

    const int cl = tid & 15;        // column lane within 16-col slab
    const int bq = tid >> 4;        // 0..15 -> batch pair (2 batches/thread)
    const int b0 = bq * 2, b1 = bq * 2 + 1;

    for (int t = 0; t < NSTEP; t++) {
        const float* hprev = (t == 0) ? dec_hidden
                                      : g_h + (long long)(t - 1) * BB * HH;

        // ---- Phase A: hW2 / gh_zr = h_prev @ [W2 | Wh[:, :1024]]
        {
            int c = bid * 16 + cl;                 // 0..1535
            const float* wcol; int ldw;
            if (c < 512) { wcol = W2 + c;         ldw = 512; }
            else         { wcol = Wh + (c - 512); ldw = H3;  }
            const float* h0 = hprev + b0 * HH;
            const float* h1 = hprev + b1 * HH;
            float a0 = 0.f, a1 = 0.f;
#pragma unroll 8
            for (int k = 0; k < HH; k++) {
                float w = __ldg(wcol + k * ldw);
                a0 += h0[k] * w;
                a1 += h1[k] * w;
            }
            if (c < 512) {
                g_hW2[b0 * HH + c] = a0;
                g_hW2[b1 * HH + c] = a1;
            } else {
                g_ghzr[b0 * 1024 + (c - 512)] = a0;
                g_ghzr[b1 * 1024 + (c - 512)] = a1;
            }
        }
        gbar();

        // ---- Phase B: scores + softmax (32 active blocks, one per batch)
        if (bid < BB) {
            int b = bid;
            for (int i = tid; i < HH; i += 256) {
                s_hv[i] = g_hW2[b * HH + i];
                s_vv[i] = v_a[i];
            }
            __syncthreads();
            int warp = tid >> 5, lane = tid & 31;
            for (int s = warp; s < SS; s += 8) {
                const float* e = g_encCat + ((long long)(b * SS + s)) * 2048;
                float sum = 0.f;
#pragma unroll
                for (int i = 0; i < 16; i++) {
                    int a = i * 32 + lane;
                    sum += tanh_approx(e[a] + s_hv[a]) * s_vv[a];
                }
#pragma unroll
                for (int o = 16; o > 0; o >>= 1)
                    sum += __shfl_xor_sync(0xffffffffu, sum, o);
                if (lane == 0) s_sc[s] = sum;
            }
            __syncthreads();
            // softmax over 128 scores
            if (tid < SS) s_red[tid] = s_sc[tid];
            __syncthreads();
            for (int o = 64; o > 0; o >>= 1) {
                if (tid < o) s_red[tid] = fmaxf(s_red[tid], s_red[tid + o]);
                __syncthreads();
            }
            float mx = s_red[0];
            __syncthreads();
            if (tid < SS) s_red[tid] = __expf(s_sc[tid] - mx);
            __syncthreads();
            for (int o = 64; o > 0; o >>= 1) {
                if (tid < o) s_red[tid] += s_red[tid + o];
                __syncthreads();
            }
            float ssum = s_red[0];
            __syncthreads();
            if (tid < SS) g_attn[b * SS + tid] = __expf(s_sc[tid] - mx) / ssum;
        }
        gbar();

        // ---- Phase C: gx = attn-weighted encWx + gxemb; gates z, r*h, gx3
        {
            int j = bid * 16 + cl;                 // 0..1535
            const float* e0 = g_encCat + (long long)(b0 * SS) * 2048 + 512 + j;
            const float* e1 = g_encCat + (long long)(b1 * SS) * 2048 + 512 + j;
            const float* at0 = g_attn + b0 * SS;
            const float* at1 = g_attn + b1 * SS;
            float a0 = 0.f, a1 = 0.f;
#pragma unroll 4
            for (int s = 0; s < SS; s++) {
                a0 += at0[s] * e0[(long long)s * 2048];
                a1 += at1[s] * e1[(long long)s * 2048];
            }
            a0 += g_gxemb[((long long)t * BB + b0) * H3 + j];
            a1 += g_gxemb[((long long)t * BB + b1) * H3 + j];
            if (j < 512) {
                g_z[b0 * HH + j] = fast_sig(a0 + g_ghzr[b0 * 1024 + j]);
                g_z[b1 * HH + j] = fast_sig(a1 + g_ghzr[b1 * 1024 + j]);
            } else if (j < 1024) {
                int jj = j - 512;
                float r0 = fast_sig(a0 + g_ghzr[b0 * 1024 + j]);
                float r1 = fast_sig(a1 + g_ghzr[b1 * 1024 + j]);
                g_rh[b0 * HH + jj] = r0 * hprev[b0 * HH + jj];
                g_rh[b1 * HH + jj] = r1 * hprev[b1 * HH + jj];
            } else {
                g_gx3[b0 * HH + (j - 1024)] = a0;
                g_gx3[b1 * HH + (j - 1024)] = a1;
            }
        }
        gbar();

        // ---- Phase D: hh = tanh(gx3 + rh @ Wh[:,1024:]); blend (32 blocks)
        if (bid < 32) {
            int c = bid * 16 + cl;                 // 0..511
            const float* wc = Wh + 1024 + c;
            const float* r0 = g_rh + b0 * HH;
            const float* r1 = g_rh + b1 * HH;
            float a0 = 0.f, a1 = 0.f;
#pragma unroll 8
            for (int k = 0; k < HH; k++) {
                float w = __ldg(wc + k * H3);
                a0 += r0[k] * w;
                a1 += r1[k] * w;
            }
            float hh0 = fast_tanh(g_gx3[b0 * HH + c] + a0);
            float hh1 = fast_tanh(g_gx3[b1 * HH + c] + a1);
            float z0 = g_z[b0 * HH + c], z1 = g_z[b1 * HH + c];
            float hp0 = hprev[b0 * HH + c], hp1 = hprev[b1 * HH + c];
            g_h[((long long)t * BB + b0) * HH + c] = z0 * hp0 + (1.f - z0) * hh0;
            g_h[((long long)t * BB + b1) * HH + c] = z1 * hp1 + (1.f - z1) * hh1;
        }
        gbar();
    }
}

// final hidden state copy: h_fin = h at t = NSTEP-1
__global__ void k_copyh(float* __restrict__ out)
{
    int i = blockIdx.x * 256 + threadIdx.x;  // 0..16383
    out[i] = g_h[(long long)(NSTEP - 1) * BB * HH + i];
}

extern "C" void kernel_launch(void* const* d_in, const int* in_sizes, int n_in,
                              void* d_out, int out_size)
{
    const int*   dec_input  = (const int*)  d_in[0];
    const float* dec_hidden = (const float*)d_in[1];
    const float* enc_output = (const float*)d_in[2];
    const int*   dec_target = (const int*)  d_in[3];
    const float* embedding  = (const float*)d_in[4];
    const float* W1  = (const float*)d_in[5];
    const float* W2  = (const float*)d_in[6];
    const float* v_a = (const float*)d_in[7];
    const float* Wx  = (const float*)d_in[8];
    const float* Wh  = (const float*)d_in[9];
    const float* b_g = (const float*)d_in[10];
    const float* Wo  = (const float*)d_in[11];
    const float* bo  = (const float*)d_in[12];
    float* out = (float*)d_out;

    // Precompute 1: encCat = enc @ [W1 | Wx_top]   (4096 x 2048, K=512)
    gemm_k<0><<<dim3(16, 32), 256>>>(enc_output, W1, Wx, nullptr, nullptr,
                                     nullptr, nullptr, nullptr, nullptr,
                                     4096, 512);
    // Precompute 2: gxemb = emb[tok] @ Wx_bot + b_g (2016 x 1536, K=256)
    gemm_k<1><<<dim3(12, 16), 256>>>(nullptr, nullptr, Wx, nullptr, b_g,
                                     dec_input, dec_target, embedding, nullptr,
                                     2016, 256);
    // Fused persistent recurrence: 63 steps in ONE launch
    k_recur<<<NB, 256>>>(dec_hidden, W2, Wh, v_a);
    // Deferred pred GEMM: (2016 x 32000, K=512), scattered to (b, t, v)
    gemm_k<2><<<dim3(250, 16), 256>>>(nullptr, nullptr, nullptr, Wo, bo,
                                      nullptr, nullptr, nullptr, out,
                                      2016, 512);
    // h_fin
    if ((long long)out_size >= OUT_PRED + BB * HH)
        k_copyh<<<64, 256>>>(out + OUT_PRED);
}

// round 7
// speedup vs baseline: 1.2599x; 1.2599x over previous
#include <cuda_runtime.h>
#include <cuda_bf16.h>

// Problem constants
#define BV     32000   // vocab
#define EE     256     // embed dim
#define HH     512     // hidden
#define SS     128     // enc seq len
#define TT     64      // dec len
#define BB     32      // batch
#define NSTEP  63      // T_DEC - 1
#define H3     1536    // 3*H
#define OUT_PRED (64512000LL)   // B * NSTEP * V

// ---------------- scratch (device globals; no allocation allowed) ----------
__device__ float g_encCat[4096 * 2048];        // [b*128+s][0:512)=enc@W1, [512:2048)=enc@Wx_top
__device__ float g_gxemb [NSTEP * BB * H3];    // emb@Wx_bot + b_g, all steps
__device__ float g_h     [NSTEP * BB * HH];    // h_t for all steps
__device__ float g_pp    [4 * BB * H3];        // hproj k-partials [kc][b][1536]
__device__ float g_ph    [4 * BB * HH];        // hh    k-partials [kc][b][512]
__device__ float g_z     [BB * HH];
__device__ float g_rh    [BB * HH];
__device__ float g_gx3   [BB * HH];

// ---------------- helpers ---------------------------------------------------
__device__ __forceinline__ unsigned long long dup2(float b) {
    unsigned long long r;
    unsigned int u = __float_as_uint(b);
    asm("mov.b64 %0, {%1, %1};" : "=l"(r) : "r"(u));
    return r;
}
__device__ __forceinline__ void fma2(unsigned long long& d,
                                     unsigned long long a,
                                     unsigned long long b) {
    asm("fma.rn.f32x2 %0, %1, %2, %3;" : "=l"(d) : "l"(a), "l"(b), "l"(d));
}
__device__ __forceinline__ float fast_tanh(float x) {      // exact identity
    float e = __expf(2.0f * x);
    return 1.0f - 2.0f / (e + 1.0f);
}
__device__ __forceinline__ float fast_sig(float x) {
    return 1.0f / (1.0f + __expf(-x));
}
__device__ __forceinline__ float tanh_approx(float x) {    // 1 MUFU, ~6e-4 abs
    float y;
    asm("tanh.approx.f32 %0, %1;" : "=f"(y) : "f"(x));
    return y;
}

// ---------------- generic 128x128 tiled fp32 GEMM with f32x2 FMAs -----------
// MODE 0: C=g_encCat : A=enc(4096x512),         B=[W1 | Wx_top](512x2048)
// MODE 1: C=g_gxemb  : A=emb[tok(m)](2016x256), B=Wx_bot(256x1536), +b_g
// MODE 2: C=preds    : A=g_h(2016x512),         B=Wo(512x32000), +bo, scatter
template<int MODE>
__global__ __launch_bounds__(256, 2)
void gemm_k(const float* __restrict__ A,  const float* __restrict__ W1,
            const float* __restrict__ Wx, const float* __restrict__ Wo,
            const float* __restrict__ bias,
            const int*   __restrict__ dinp, const int* __restrict__ dtgt,
            const float* __restrict__ emb, float* __restrict__ C,
            int M, int K)
{
    __shared__ __align__(16) float As[16][132];
    __shared__ __align__(16) float Bs[16][132];

    const int tid = threadIdx.x;
    const int tx = tid & 15;
    const int ty = tid >> 4;
    const int bn = blockIdx.x, bm = blockIdx.y;

    unsigned long long acc[4][8];
#pragma unroll
    for (int i = 0; i < 4; i++)
#pragma unroll
        for (int j = 0; j < 8; j++) acc[i][j] = 0ULL;

    const int nTiles = K >> 4;
    for (int kt = 0; kt < nTiles; ++kt) {
#pragma unroll
        for (int q = 0; q < 2; q++) {
            int l = tid * 2 + q;          // 0..511
            int r = l >> 2;
            int cseg = l & 3;
            int rowg = bm * 128 + r; if (rowg > M - 1) rowg = M - 1;
            const float* ap;
            if (MODE == 1) {
                int t = rowg >> 5, b = rowg & 31;
                int tok = (t == 0) ? dinp[b] : dtgt[b * TT + t];
                ap = emb + (long long)tok * EE;
            } else if (MODE == 2) {
                ap = g_h + (long long)rowg * HH;
            } else {
                ap = A + (long long)rowg * K;
            }
            float4 v = *reinterpret_cast<const float4*>(ap + kt * 16 + cseg * 4);
            As[cseg * 4 + 0][r] = v.x; As[cseg * 4 + 1][r] = v.y;
            As[cseg * 4 + 2][r] = v.z; As[cseg * 4 + 3][r] = v.w;
            int kr = l >> 5;
            int nseg = l & 31;
            int kg = kt * 16 + kr;
            int n = bn * 128 + nseg * 4;
            const float* bp;
            if (MODE == 0) {
                bp = (n < 512) ? (W1 + (long long)kg * 512 + n)
                               : (Wx + (long long)kg * H3 + (n - 512));
            } else if (MODE == 1) {
                bp = Wx + (long long)(512 + kg) * H3 + n;
            } else {
                bp = Wo + (long long)kg * BV + n;
            }
            *reinterpret_cast<float4*>(&Bs[kr][nseg * 4]) =
                *reinterpret_cast<const float4*>(bp);
        }
        __syncthreads();
#pragma unroll
        for (int k = 0; k < 16; k++) {
            const unsigned long long* arow =
                reinterpret_cast<const unsigned long long*>(&As[k][0]);
            unsigned long long a0 = arow[ty * 4 + 0];
            unsigned long long a1 = arow[ty * 4 + 1];
            unsigned long long a2 = arow[ty * 4 + 2];
            unsigned long long a3 = arow[ty * 4 + 3];
            float4 b0 = *reinterpret_cast<const float4*>(&Bs[k][tx * 4]);
            float4 b1 = *reinterpret_cast<const float4*>(&Bs[k][64 + tx * 4]);
            float bf[8] = {b0.x, b0.y, b0.z, b0.w, b1.x, b1.y, b1.z, b1.w};
#pragma unroll
            for (int j = 0; j < 8; j++) {
                unsigned long long dj = dup2(bf[j]);
                fma2(acc[0][j], a0, dj);
                fma2(acc[1][j], a1, dj);
                fma2(acc[2][j], a2, dj);
                fma2(acc[3][j], a3, dj);
            }
        }
        __syncthreads();
    }

    const int nA = bn * 128 + tx * 4;
    const int nB = nA + 64;
#pragma unroll
    for (int i2 = 0; i2 < 4; i2++) {
#pragma unroll
        for (int p = 0; p < 2; p++) {
            int m = bm * 128 + ty * 8 + i2 * 2 + p;
            if (m >= M) continue;
            float vals[8];
#pragma unroll
            for (int j = 0; j < 8; j++) {
                unsigned long long u = acc[i2][j];
                unsigned int w = (p == 0) ? (unsigned int)u
                                          : (unsigned int)(u >> 32);
                vals[j] = __uint_as_float(w);
            }
            if (MODE == 0) {
                float* cp = g_encCat + (long long)m * 2048;
                *reinterpret_cast<float4*>(cp + nA) =
                    make_float4(vals[0], vals[1], vals[2], vals[3]);
                *reinterpret_cast<float4*>(cp + nB) =
                    make_float4(vals[4], vals[5], vals[6], vals[7]);
            } else if (MODE == 1) {
                float* cp = g_gxemb + (long long)m * H3;
                float4 ba = *reinterpret_cast<const float4*>(bias + nA);
                float4 bb = *reinterpret_cast<const float4*>(bias + nB);
                *reinterpret_cast<float4*>(cp + nA) =
                    make_float4(vals[0] + ba.x, vals[1] + ba.y,
                                vals[2] + ba.z, vals[3] + ba.w);
                *reinterpret_cast<float4*>(cp + nB) =
                    make_float4(vals[4] + bb.x, vals[5] + bb.y,
                                vals[6] + bb.z, vals[7] + bb.w);
            } else {
                int t = m >> 5, b = m & 31;   // m = t*32 + b
                float* cp = C + (long long)b * (NSTEP * (long long)BV)
                              + (long long)t * BV;
                float4 ba = *reinterpret_cast<const float4*>(bias + nA);
                float4 bb = *reinterpret_cast<const float4*>(bias + nB);
                *reinterpret_cast<float4*>(cp + nA) =
                    make_float4(vals[0] + ba.x, vals[1] + ba.y,
                                vals[2] + ba.z, vals[3] + ba.w);
                *reinterpret_cast<float4*>(cp + nB) =
                    make_float4(vals[4] + bb.x, vals[5] + bb.y,
                                vals[6] + bb.z, vals[7] + bb.w);
            }
        }
    }
}

// ---------------- per-step: hproj partials ----------------------------------
// grid (4 kc, 12 bc), 256 thr. Block: 128 cols x 32 batches x 128 k-chunk.
// Virtual cols 0..511 -> W2, 512..1535 -> Wh[:, 0:1024].
// Weights read ONCE per step; h transposed in smem; FMA2 over batch pairs.
__global__ __launch_bounds__(256)
void k_hproj(const float* __restrict__ dec_hidden,
             const float* __restrict__ W2,
             const float* __restrict__ Wh, int t)
{
    const int kc = blockIdx.x, bc = blockIdx.y;
    const int kbase = kc * 128, cbase = bc * 128;
    const int tid = threadIdx.x;
    const float* hprev = (t == 0) ? dec_hidden
                                  : g_h + (long long)(t - 1) * BB * HH;

    __shared__ float hT[128 * 34];   // hT[k*34 + b]
    for (int i = tid; i < 4096; i += 256) {
        int b = i >> 7, k = i & 127;
        hT[k * 34 + b] = hprev[b * HH + kbase + k];
    }
    __syncthreads();

    const int cq = tid & 31;             // col quad
    const int bq = tid >> 5;             // batch quad (0..7)
    const int c0 = cbase + cq * 4;
    const float* wrow; int ldw;
    if (c0 < 512) { wrow = W2 + c0;         ldw = 512; }
    else          { wrow = Wh + (c0 - 512); ldw = H3;  }

    unsigned long long acc[4][2];
#pragma unroll
    for (int c = 0; c < 4; c++) { acc[c][0] = 0ULL; acc[c][1] = 0ULL; }

#pragma unroll 4
    for (int k = 0; k < 128; k++) {
        float4 w = *reinterpret_cast<const float4*>(
            wrow + (long long)(kbase + k) * ldw);
        unsigned long long h01 =
            *reinterpret_cast<const unsigned long long*>(&hT[k * 34 + bq * 4]);
        unsigned long long h23 =
            *reinterpret_cast<const unsigned long long*>(&hT[k * 34 + bq * 4 + 2]);
        unsigned long long w0 = dup2(w.x), w1 = dup2(w.y),
                           w2 = dup2(w.z), w3 = dup2(w.w);
        fma2(acc[0][0], h01, w0); fma2(acc[0][1], h23, w0);
        fma2(acc[1][0], h01, w1); fma2(acc[1][1], h23, w1);
        fma2(acc[2][0], h01, w2); fma2(acc[2][1], h23, w2);
        fma2(acc[3][0], h01, w3); fma2(acc[3][1], h23, w3);
    }

#pragma unroll
    for (int c = 0; c < 4; c++) {
#pragma unroll
        for (int p = 0; p < 2; p++) {
            int b = bq * 4 + p * 2;
            unsigned long long u = acc[c][p];
            g_pp[(kc * BB + b)     * H3 + c0 + c] =
                __uint_as_float((unsigned int)u);
            g_pp[(kc * BB + b + 1) * H3 + c0 + c] =
                __uint_as_float((unsigned int)(u >> 32));
        }
    }
}

// ---------------- per-step: fused score+softmax+mix+gates -------------------
// grid 64: b = bid>>1, jhalf = bid&1 (j range jhalf*768..+768).
// Scores/softmax duplicated per half (cheap, keeps blocks independent).
__global__ __launch_bounds__(256)
void k_fused(const float* __restrict__ v_a,
             const float* __restrict__ dec_hidden, int t)
{
    const int b = blockIdx.x >> 1;
    const int jhalf = blockIdx.x & 1;
    const int tid = threadIdx.x;
    const float* hprev = (t == 0) ? dec_hidden
                                  : g_h + (long long)(t - 1) * BB * HH;

    __shared__ float s_hv[512];
    __shared__ float s_zr[1024];
    __shared__ float s_vv[512];
    __shared__ float s_at[SS];
    __shared__ float s_red[SS];

    // reduce hproj partials (deterministic order)
    for (int j = tid; j < H3; j += 256) {
        float v = g_pp[(0 * BB + b) * H3 + j] + g_pp[(1 * BB + b) * H3 + j]
                + g_pp[(2 * BB + b) * H3 + j] + g_pp[(3 * BB + b) * H3 + j];
        if (j < 512) s_hv[j] = v; else s_zr[j - 512] = v;
    }
    for (int j = tid; j < 512; j += 256) s_vv[j] = v_a[j];
    __syncthreads();

    // scores: warp per s
    {
        int warp = tid >> 5, lane = tid & 31;
        for (int s = warp; s < SS; s += 8) {
            const float* e = g_encCat + ((long long)(b * SS + s)) * 2048;
            float sum = 0.f;
#pragma unroll
            for (int i = 0; i < 16; i++) {
                int a = i * 32 + lane;
                sum += tanh_approx(e[a] + s_hv[a]) * s_vv[a];
            }
#pragma unroll
            for (int o = 16; o > 0; o >>= 1)
                sum += __shfl_xor_sync(0xffffffffu, sum, o);
            if (lane == 0) s_at[s] = sum;
        }
    }
    __syncthreads();

    // softmax over 128
    if (tid < SS) s_red[tid] = s_at[tid];
    __syncthreads();
    for (int o = 64; o > 0; o >>= 1) {
        if (tid < o) s_red[tid] = fmaxf(s_red[tid], s_red[tid + o]);
        __syncthreads();
    }
    float mx = s_red[0];
    __syncthreads();
    if (tid < SS) s_red[tid] = __expf(s_at[tid] - mx);
    __syncthreads();
    for (int o = 64; o > 0; o >>= 1) {
        if (tid < o) s_red[tid] += s_red[tid + o];
        __syncthreads();
    }
    float ssum = s_red[0];
    __syncthreads();
    if (tid < SS) s_at[tid] = __expf(s_at[tid] - mx) / ssum;
    __syncthreads();

    // mix + gates for this j-half
    const float* gxe = g_gxemb + ((long long)t * BB + b) * H3;
    for (int jj = tid; jj < 768; jj += 256) {
        int j = jhalf * 768 + jj;
        const float* e = g_encCat + (long long)b * SS * 2048 + 512 + j;
        float acc = 0.f;
#pragma unroll 8
        for (int s = 0; s < SS; s++) acc += s_at[s] * e[(long long)s * 2048];
        acc += gxe[j];
        if (j < 512) {
            g_z[b * HH + j] = fast_sig(acc + s_zr[j]);
        } else if (j < 1024) {
            int c = j - 512;
            float r = fast_sig(acc + s_zr[j]);
            g_rh[b * HH + c] = r * hprev[b * HH + c];
        } else {
            g_gx3[b * HH + (j - 1024)] = acc;
        }
    }
}

// ---------------- per-step: hh partials (rh @ Wh[:,1024:]) ------------------
// grid (4 kc, 4 bc), same structure as k_hproj. A = g_rh.
__global__ __launch_bounds__(256)
void k_hh(const float* __restrict__ Wh, int t)
{
    const int kc = blockIdx.x, bc = blockIdx.y;
    const int kbase = kc * 128, cbase = bc * 128;
    const int tid = threadIdx.x;

    __shared__ float hT[128 * 34];
    for (int i = tid; i < 4096; i += 256) {
        int b = i >> 7, k = i & 127;
        hT[k * 34 + b] = g_rh[b * HH + kbase + k];
    }
    __syncthreads();

    const int cq = tid & 31;
    const int bq = tid >> 5;
    const int c0 = cbase + cq * 4;
    const float* wrow = Wh + 1024 + c0;

    unsigned long long acc[4][2];
#pragma unroll
    for (int c = 0; c < 4; c++) { acc[c][0] = 0ULL; acc[c][1] = 0ULL; }

#pragma unroll 4
    for (int k = 0; k < 128; k++) {
        float4 w = *reinterpret_cast<const float4*>(
            wrow + (long long)(kbase + k) * H3);
        unsigned long long h01 =
            *reinterpret_cast<const unsigned long long*>(&hT[k * 34 + bq * 4]);
        unsigned long long h23 =
            *reinterpret_cast<const unsigned long long*>(&hT[k * 34 + bq * 4 + 2]);
        unsigned long long w0 = dup2(w.x), w1 = dup2(w.y),
                           w2 = dup2(w.z), w3 = dup2(w.w);
        fma2(acc[0][0], h01, w0); fma2(acc[0][1], h23, w0);
        fma2(acc[1][0], h01, w1); fma2(acc[1][1], h23, w1);
        fma2(acc[2][0], h01, w2); fma2(acc[2][1], h23, w2);
        fma2(acc[3][0], h01, w3); fma2(acc[3][1], h23, w3);
    }

#pragma unroll
    for (int c = 0; c < 4; c++) {
#pragma unroll
        for (int p = 0; p < 2; p++) {
            int b = bq * 4 + p * 2;
            unsigned long long u = acc[c][p];
            g_ph[(kc * BB + b)     * HH + c0 + c] =
                __uint_as_float((unsigned int)u);
            g_ph[(kc * BB + b + 1) * HH + c0 + c] =
                __uint_as_float((unsigned int)(u >> 32));
        }
    }
}

// ---------------- per-step: reduce hh partials, tanh, blend -----------------
__global__ void k_blend(const float* __restrict__ dec_hidden, int t)
{
    int b = blockIdx.x;
    int c = threadIdx.x;   // 0..511
    const float* hprev = (t == 0) ? dec_hidden
                                  : g_h + (long long)(t - 1) * BB * HH;
    float v = g_ph[(0 * BB + b) * HH + c] + g_ph[(1 * BB + b) * HH + c]
            + g_ph[(2 * BB + b) * HH + c] + g_ph[(3 * BB + b) * HH + c];
    float hh = fast_tanh(g_gx3[b * HH + c] + v);
    float z  = g_z[b * HH + c];
    float hp = hprev[b * HH + c];
    g_h[((long long)t * BB + b) * HH + c] = z * hp + (1.f - z) * hh;
}

// final hidden state copy
__global__ void k_copyh(float* __restrict__ out)
{
    int i = blockIdx.x * 256 + threadIdx.x;
    out[i] = g_h[(long long)(NSTEP - 1) * BB * HH + i];
}

extern "C" void kernel_launch(void* const* d_in, const int* in_sizes, int n_in,
                              void* d_out, int out_size)
{
    const int*   dec_input  = (const int*)  d_in[0];
    const float* dec_hidden = (const float*)d_in[1];
    const float* enc_output = (const float*)d_in[2];
    const int*   dec_target = (const int*)  d_in[3];
    const float* embedding  = (const float*)d_in[4];
    const float* W1  = (const float*)d_in[5];
    const float* W2  = (const float*)d_in[6];
    const float* v_a = (const float*)d_in[7];
    const float* Wx  = (const float*)d_in[8];
    const float* Wh  = (const float*)d_in[9];
    const float* b_g = (const float*)d_in[10];
    const float* Wo  = (const float*)d_in[11];
    const float* bo  = (const float*)d_in[12];
    float* out = (float*)d_out;

    // Precompute 1: encCat = enc @ [W1 | Wx_top]   (4096 x 2048, K=512)
    gemm_k<0><<<dim3(16, 32), 256>>>(enc_output, W1, Wx, nullptr, nullptr,
                                     nullptr, nullptr, nullptr, nullptr,
                                     4096, 512);
    // Precompute 2: gxemb = emb[tok] @ Wx_bot + b_g (2016 x 1536, K=256)
    gemm_k<1><<<dim3(12, 16), 256>>>(nullptr, nullptr, Wx, nullptr, b_g,
                                     dec_input, dec_target, embedding, nullptr,
                                     2016, 256);
    // Recurrence: 63 steps x 4 kernels
    for (int t = 0; t < NSTEP; t++) {
        k_hproj<<<dim3(4, 12), 256>>>(dec_hidden, W2, Wh, t);
        k_fused<<<64, 256>>>(v_a, dec_hidden, t);
        k_hh   <<<dim3(4, 4), 256>>>(Wh, t);
        k_blend<<<32, 512>>>(dec_hidden, t);
    }
    // Deferred pred GEMM: (2016 x 32000, K=512), scattered to (b, t, v)
    gemm_k<2><<<dim3(250, 16), 256>>>(nullptr, nullptr, nullptr, Wo, bo,
                                      nullptr, nullptr, nullptr, out,
                                      2016, 512);
    // h_fin
    if ((long long)out_size >= OUT_PRED + BB * HH)
        k_copyh<<<64, 256>>>(out + OUT_PRED);
}